// round 11
// baseline (speedup 1.0000x reference)
#include <cuda_runtime.h>

#define H      512
#define TSTEPS 98
#define INW    8
#define NPIX   784
#define OUTN   10
#define NBATCH 512
#define SPB    4                 // samples per block
#define NBLK   (NBATCH / SPB)    // 128 blocks
#define NTHR   512               // thread j owns neuron j in all 3 layers

// Transposed weights [matrix][i][j]:
// 0: h2h1, 1: i2h2, 2: h2h2, 3: i2h3, 4: h2h3
__device__ float g_wt[5 * H * H];

typedef unsigned long long ull;

// ---------------------------------------------------------------------------
// Cephes/glibc-class expf (verified bit-identical to reference on all taus).
// ---------------------------------------------------------------------------
__device__ __forceinline__ float xla_cephes_expf(float x) {
    const float LOG2EF = 1.44269504088896341f;
    const float C1 = 0.693359375f;
    const float C2 = -2.12194440e-4f;
    const float p0 = 1.9875691500E-4f;
    const float p1 = 1.3981999507E-3f;
    const float p2 = 8.3334519073E-3f;
    const float p3 = 4.1665795894E-2f;
    const float p4 = 1.6666665459E-1f;
    const float p5 = 5.0000001201E-1f;

    x = fminf(x, 88.3762626647950f);
    x = fmaxf(x, -88.3762626647949f);

    float fx = floorf(__fadd_rn(__fmul_rn(x, LOG2EF), 0.5f));
    x = __fsub_rn(x, __fmul_rn(fx, C1));
    x = __fsub_rn(x, __fmul_rn(fx, C2));

    float z = __fmul_rn(x, x);
    float y = p0;
    y = __fadd_rn(__fmul_rn(y, x), p1);
    y = __fadd_rn(__fmul_rn(y, x), p2);
    y = __fadd_rn(__fmul_rn(y, x), p3);
    y = __fadd_rn(__fmul_rn(y, x), p4);
    y = __fadd_rn(__fmul_rn(y, x), p5);
    y = __fadd_rn(__fmul_rn(y, z), x);
    y = __fadd_rn(1.0f, y);

    int n = (int)fx;
    return __int_as_float(__float_as_int(y) + (n << 23));
}

__device__ __forceinline__ ull ffma2(ull a, ull b, ull c) {
    ull d;
    asm("fma.rn.f32x2 %0, %1, %2, %3;" : "=l"(d) : "l"(a), "l"(b), "l"(c));
    return d;
}
__device__ __forceinline__ ull add2(ull a, ull b) {
    ull d;
    asm("add.rn.f32x2 %0, %1, %2;" : "=l"(d) : "l"(a), "l"(b));
    return d;
}
__device__ __forceinline__ ull dup2(float w) {
    ull d; unsigned u = __float_as_uint(w);
    asm("mov.b64 %0, {%1, %1};" : "=l"(d) : "r"(u));
    return d;
}
__device__ __forceinline__ float2 unpack2(ull v) {
    float2 f;
    asm("mov.b64 {%0, %1}, %2;" : "=f"(f.x), "=f"(f.y) : "l"(v));
    return f;
}

// ALIF update, FMA-contracted (LLVM AllowFPOpFusion::Fast) — the verified
// bit-exact numeric contract from R9. DO NOT CHANGE.
__device__ __forceinline__ void alif_step(float h, float& m, float& b, float sold,
                                          float alpha, float oma, float ro, float omro,
                                          float& snew) {
    b = __fmaf_rn(ro, b, __fmul_rn(omro, sold));
    float Bth = __fmaf_rn(1.8f, b, 0.01f);
    float X = __fmaf_rn(m, alpha, __fmul_rn(oma, h));
    m = __fmaf_rn(-Bth, sold, X);
    snew = (__fsub_rn(m, Bth) > 0.0f) ? 1.0f : 0.0f;
}

// ---------------------------------------------------------------------------
// Tiled transpose of the 5 big weight matrices into g_wt [m][i][j].
// grid (16,16,5), block (32,32)
// ---------------------------------------------------------------------------
__global__ void transpose5_kernel(const float* __restrict__ w0,
                                  const float* __restrict__ w1,
                                  const float* __restrict__ w2,
                                  const float* __restrict__ w3,
                                  const float* __restrict__ w4) {
    __shared__ float tile[32][33];
    const float* src;
    switch (blockIdx.z) {
        case 0: src = w0; break;
        case 1: src = w1; break;
        case 2: src = w2; break;
        case 3: src = w3; break;
        default: src = w4; break;
    }
    int i0 = blockIdx.x * 32;   // column of original (input dim)
    int j0 = blockIdx.y * 32;   // row of original (output neuron)
    int tx = threadIdx.x, ty = threadIdx.y;
    tile[ty][tx] = src[(j0 + ty) * H + (i0 + tx)];
    __syncthreads();
    g_wt[(size_t)blockIdx.z * H * H + (size_t)(i0 + ty) * H + (j0 + tx)] = tile[tx][ty];
}

// ---------------------------------------------------------------------------
// Main persistent SRNN kernel. One block = 4 samples, thread j = neuron j.
// Double-buffered spikes: 6 * [H][SPB] = 48KB dynamic smem.
// Event-driven: weight LDG predicated off when no sample fired at input i
// (exact: lanes with s=0 contribute w*0 = 0; skipped loads use w=0).
// ---------------------------------------------------------------------------
extern __shared__ float smem[];

__global__ void __launch_bounds__(NTHR, 1) srnn_kernel(
    const float* __restrict__ x,
    const float* __restrict__ i2h1_w, const float* __restrict__ i2h1_b,
    const float* __restrict__ h2h1_b,
    const float* __restrict__ i2h2_b, const float* __restrict__ h2h2_b,
    const float* __restrict__ i2h3_b, const float* __restrict__ h2h3_b,
    const float* __restrict__ h2o_w,  const float* __restrict__ h2o_b,
    const float* __restrict__ tau_adp_h1, const float* __restrict__ tau_adp_h2,
    const float* __restrict__ tau_adp_h3,
    const float* __restrict__ tau_m_h1,   const float* __restrict__ tau_m_h2,
    const float* __restrict__ tau_m_h3,
    float* __restrict__ out)
{
    const int j    = threadIdx.x;
    const int smp0 = blockIdx.x * SPB;

    float* buf0 = smem;
    float* spk1c = buf0 + 0 * H * SPB;  float* spk1n = buf0 + 1 * H * SPB;
    float* spk2c = buf0 + 2 * H * SPB;  float* spk2n = buf0 + 3 * H * SPB;
    float* spk3c = buf0 + 4 * H * SPB;  float* spk3n = buf0 + 5 * H * SPB;

    {
        float4 z = make_float4(0.f, 0.f, 0.f, 0.f);
        *(float4*)(spk1c + j * SPB) = z;  *(float4*)(spk1n + j * SPB) = z;
        *(float4*)(spk2c + j * SPB) = z;  *(float4*)(spk2n + j * SPB) = z;
        *(float4*)(spk3c + j * SPB) = z;  *(float4*)(spk3n + j * SPB) = z;
    }

    const float a1 = xla_cephes_expf(__fdiv_rn(-1.0f, tau_m_h1[j]));
    const float a2 = xla_cephes_expf(__fdiv_rn(-1.0f, tau_m_h2[j]));
    const float a3 = xla_cephes_expf(__fdiv_rn(-1.0f, tau_m_h3[j]));
    const float r1 = xla_cephes_expf(__fdiv_rn(-1.0f, tau_adp_h1[j]));
    const float r2 = xla_cephes_expf(__fdiv_rn(-1.0f, tau_adp_h2[j]));
    const float r3 = xla_cephes_expf(__fdiv_rn(-1.0f, tau_adp_h3[j]));
    const float oma1 = __fsub_rn(1.0f, a1), oma2 = __fsub_rn(1.0f, a2),
                oma3 = __fsub_rn(1.0f, a3);
    const float omr1 = __fsub_rn(1.0f, r1), omr2 = __fsub_rn(1.0f, r2),
                omr3 = __fsub_rn(1.0f, r3);

    const float bi1 = i2h1_b[j], bh1 = h2h1_b[j];
    const ull bi2d = dup2(i2h2_b[j]), bh2d = dup2(h2h2_b[j]);
    const ull bi3d = dup2(i2h3_b[j]), bh3d = dup2(h2h3_b[j]);

    float wi1[INW];
    {
        float4 wa = *(const float4*)(i2h1_w + j * INW);
        float4 wb = *(const float4*)(i2h1_w + j * INW + 4);
        wi1[0] = wa.x; wi1[1] = wa.y; wi1[2] = wa.z; wi1[3] = wa.w;
        wi1[4] = wb.x; wi1[5] = wb.y; wi1[6] = wb.z; wi1[7] = wb.w;
    }

    float m1[SPB], m2[SPB], m3[SPB], b1[SPB], b2[SPB], b3[SPB], c3[SPB];
#pragma unroll
    for (int s = 0; s < SPB; ++s) {
        m1[s] = m2[s] = m3[s] = 0.0f;
        b1[s] = b2[s] = b3[s] = 0.01f;
        c3[s] = 0.0f;
    }

    const float* wt_h2h1 = g_wt + 0 * H * H + j;
    const float* wt_i2h2 = g_wt + 1 * H * H + j;
    const float* wt_h2h2 = g_wt + 2 * H * H + j;
    const float* wt_i2h3 = g_wt + 3 * H * H + j;
    const float* wt_h2h3 = g_wt + 4 * H * H + j;

    __syncthreads();

    for (int t = 0; t < TSTEPS; ++t) {
        const int st = (t * INW < TSTEPS - INW) ? t * INW : (NPIX - INW);

        // ================= layer 1 =================
        ull accH[2] = {0ull, 0ull};
#pragma unroll 4
        for (int i = 0; i < H; ++i) {
            ulonglong2 sv = *(const ulonglong2*)(spk1c + i * SPB);
            float w = 0.0f;
            if (sv.x | sv.y) w = __ldg(wt_h2h1 + (size_t)i * H);
            ull wd = dup2(w);
            accH[0] = ffma2(wd, sv.x, accH[0]);
            accH[1] = ffma2(wd, sv.y, accH[1]);
        }
        float snew[SPB];
        {
            const float* xb = x + (size_t)smp0 * NPIX + st;
            float4 so = *(float4*)(spk1c + j * SPB);
            float sold[SPB] = {so.x, so.y, so.z, so.w};
#pragma unroll
            for (int s = 0; s < SPB; ++s) {
                float4 xa = *(const float4*)(xb + (size_t)s * NPIX);
                float4 xc = *(const float4*)(xb + (size_t)s * NPIX + 4);
                float dx = __fmaf_rn(xa.x, wi1[0], 0.0f);
                dx = __fmaf_rn(xa.y, wi1[1], dx);
                dx = __fmaf_rn(xa.z, wi1[2], dx);
                dx = __fmaf_rn(xa.w, wi1[3], dx);
                dx = __fmaf_rn(xc.x, wi1[4], dx);
                dx = __fmaf_rn(xc.y, wi1[5], dx);
                dx = __fmaf_rn(xc.z, wi1[6], dx);
                dx = __fmaf_rn(xc.w, wi1[7], dx);
                float2 dh2 = unpack2(accH[s >> 1]);
                float dh = (s & 1) ? dh2.y : dh2.x;
                float h = __fadd_rn(__fadd_rn(__fadd_rn(dx, bi1), dh), bh1);
                alif_step(h, m1[s], b1[s], sold[s], a1, oma1, r1, omr1, snew[s]);
            }
        }
        *(float4*)(spk1n + j * SPB) = make_float4(snew[0], snew[1], snew[2], snew[3]);
        __syncthreads();

        // ================= layer 2 =================
        ull accI[2] = {0ull, 0ull};
        accH[0] = accH[1] = 0ull;
#pragma unroll 4
        for (int i = 0; i < H; ++i) {
            ulonglong2 sa = *(const ulonglong2*)(spk1n + i * SPB);
            ulonglong2 sb = *(const ulonglong2*)(spk2c + i * SPB);
            float wa = 0.0f, wb = 0.0f;
            if (sa.x | sa.y) wa = __ldg(wt_i2h2 + (size_t)i * H);
            if (sb.x | sb.y) wb = __ldg(wt_h2h2 + (size_t)i * H);
            ull wad = dup2(wa), wbd = dup2(wb);
            accI[0] = ffma2(wad, sa.x, accI[0]);
            accI[1] = ffma2(wad, sa.y, accI[1]);
            accH[0] = ffma2(wbd, sb.x, accH[0]);
            accH[1] = ffma2(wbd, sb.y, accH[1]);
        }
        {
            float4 so = *(float4*)(spk2c + j * SPB);
            float sold[SPB] = {so.x, so.y, so.z, so.w};
#pragma unroll
            for (int q = 0; q < 2; ++q) {
                ull h2v = add2(add2(add2(accI[q], bi2d), accH[q]), bh2d);
                float2 hv = unpack2(h2v);
                alif_step(hv.x, m2[2*q],   b2[2*q],   sold[2*q],   a2, oma2, r2, omr2, snew[2*q]);
                alif_step(hv.y, m2[2*q+1], b2[2*q+1], sold[2*q+1], a2, oma2, r2, omr2, snew[2*q+1]);
            }
        }
        *(float4*)(spk2n + j * SPB) = make_float4(snew[0], snew[1], snew[2], snew[3]);
        __syncthreads();

        // ================= layer 3 =================
        accI[0] = accI[1] = 0ull;
        accH[0] = accH[1] = 0ull;
#pragma unroll 4
        for (int i = 0; i < H; ++i) {
            ulonglong2 sa = *(const ulonglong2*)(spk2n + i * SPB);
            ulonglong2 sb = *(const ulonglong2*)(spk3c + i * SPB);
            float wa = 0.0f, wb = 0.0f;
            if (sa.x | sa.y) wa = __ldg(wt_i2h3 + (size_t)i * H);
            if (sb.x | sb.y) wb = __ldg(wt_h2h3 + (size_t)i * H);
            ull wad = dup2(wa), wbd = dup2(wb);
            accI[0] = ffma2(wad, sa.x, accI[0]);
            accI[1] = ffma2(wad, sa.y, accI[1]);
            accH[0] = ffma2(wbd, sb.x, accH[0]);
            accH[1] = ffma2(wbd, sb.y, accH[1]);
        }
        {
            float4 so = *(float4*)(spk3c + j * SPB);
            float sold[SPB] = {so.x, so.y, so.z, so.w};
#pragma unroll
            for (int q = 0; q < 2; ++q) {
                ull h2v = add2(add2(add2(accI[q], bi3d), accH[q]), bh3d);
                float2 hv = unpack2(h2v);
                alif_step(hv.x, m3[2*q],   b3[2*q],   sold[2*q],   a3, oma3, r3, omr3, snew[2*q]);
                alif_step(hv.y, m3[2*q+1], b3[2*q+1], sold[2*q+1], a3, oma3, r3, omr3, snew[2*q+1]);
            }
        }
        *(float4*)(spk3n + j * SPB) = make_float4(snew[0], snew[1], snew[2], snew[3]);
#pragma unroll
        for (int s = 0; s < SPB; ++s) c3[s] += snew[s];
        __syncthreads();

        // swap buffers
        float* tmp;
        tmp = spk1c; spk1c = spk1n; spk1n = tmp;
        tmp = spk2c; spk2c = spk2n; spk2n = tmp;
        tmp = spk3c; spk3c = spk3n; spk3n = tmp;
    }

    // ======== output: out[smp][o] = (sum_j c3[smp][j]*W[o][j]) / T + b[o] ========
    __syncthreads();
#pragma unroll
    for (int s = 0; s < SPB; ++s) buf0[s * H + j] = c3[s];
    __syncthreads();

    const int warp = j >> 5, lane = j & 31;
    for (int pair = warp; pair < SPB * OUTN; pair += NTHR / 32) {
        int s = pair / OUTN, o = pair % OUTN;
        float sum = 0.0f;
        for (int jj = lane; jj < H; jj += 32)
            sum += buf0[s * H + jj] * __ldg(h2o_w + o * H + jj);
#pragma unroll
        for (int off = 16; off > 0; off >>= 1)
            sum += __shfl_down_sync(0xffffffffu, sum, off);
        if (lane == 0)
            out[(size_t)(smp0 + s) * OUTN + o] = sum / (float)TSTEPS + h2o_b[o];
    }
}

// ---------------------------------------------------------------------------
extern "C" void kernel_launch(void* const* d_in, const int* in_sizes, int n_in,
                              void* d_out, int out_size) {
    (void)in_sizes; (void)n_in; (void)out_size;
    const float* x          = (const float*)d_in[0];
    const float* i2h1_w     = (const float*)d_in[1];
    const float* i2h1_b     = (const float*)d_in[2];
    const float* h2h1_w     = (const float*)d_in[3];
    const float* h2h1_b     = (const float*)d_in[4];
    const float* i2h2_w     = (const float*)d_in[5];
    const float* i2h2_b     = (const float*)d_in[6];
    const float* h2h2_w     = (const float*)d_in[7];
    const float* h2h2_b     = (const float*)d_in[8];
    const float* i2h3_w     = (const float*)d_in[9];
    const float* i2h3_b     = (const float*)d_in[10];
    const float* h2h3_w     = (const float*)d_in[11];
    const float* h2h3_b     = (const float*)d_in[12];
    const float* h2o_w      = (const float*)d_in[13];
    const float* h2o_b      = (const float*)d_in[14];
    const float* tau_adp_h1 = (const float*)d_in[15];
    const float* tau_adp_h2 = (const float*)d_in[16];
    const float* tau_adp_h3 = (const float*)d_in[17];
    const float* tau_m_h1   = (const float*)d_in[18];
    const float* tau_m_h2   = (const float*)d_in[19];
    const float* tau_m_h3   = (const float*)d_in[20];
    float* out = (float*)d_out;

    transpose5_kernel<<<dim3(16, 16, 5), dim3(32, 32)>>>(h2h1_w, i2h2_w, h2h2_w,
                                                         i2h3_w, h2h3_w);

    const size_t smem_bytes = 6 * H * SPB * sizeof(float);  // 48KB
    srnn_kernel<<<NBLK, NTHR, smem_bytes>>>(
        x, i2h1_w, i2h1_b, h2h1_b, i2h2_b, h2h2_b, i2h3_b, h2h3_b,
        h2o_w, h2o_b, tau_adp_h1, tau_adp_h2, tau_adp_h3,
        tau_m_h1, tau_m_h2, tau_m_h3, out);
}

// round 12
// speedup vs baseline: 3.2662x; 3.2662x over previous
#include <cuda_runtime.h>

#define H      512
#define TSTEPS 98
#define INW    8
#define NPIX   784
#define OUTN   10
#define NBATCH 512
#define SPB    4                 // samples per block
#define NBLK   (NBATCH / SPB)    // 128 blocks
#define NTHR   512               // thread j owns neuron j in all 3 layers
#define NWARP  (NTHR / 32)       // 16

// Transposed weights [matrix][i][j]:
// 0: h2h1, 1: i2h2, 2: h2h2, 3: i2h3, 4: h2h3
__device__ float g_wt[5 * H * H];

typedef unsigned long long ull;
typedef unsigned short ushort_t;

// ---------------------------------------------------------------------------
// Cephes/glibc-class expf (verified bit-identical to reference on all taus).
// ---------------------------------------------------------------------------
__device__ __forceinline__ float xla_cephes_expf(float x) {
    const float LOG2EF = 1.44269504088896341f;
    const float C1 = 0.693359375f;
    const float C2 = -2.12194440e-4f;
    const float p0 = 1.9875691500E-4f;
    const float p1 = 1.3981999507E-3f;
    const float p2 = 8.3334519073E-3f;
    const float p3 = 4.1665795894E-2f;
    const float p4 = 1.6666665459E-1f;
    const float p5 = 5.0000001201E-1f;

    x = fminf(x, 88.3762626647950f);
    x = fmaxf(x, -88.3762626647949f);

    float fx = floorf(__fadd_rn(__fmul_rn(x, LOG2EF), 0.5f));
    x = __fsub_rn(x, __fmul_rn(fx, C1));
    x = __fsub_rn(x, __fmul_rn(fx, C2));

    float z = __fmul_rn(x, x);
    float y = p0;
    y = __fadd_rn(__fmul_rn(y, x), p1);
    y = __fadd_rn(__fmul_rn(y, x), p2);
    y = __fadd_rn(__fmul_rn(y, x), p3);
    y = __fadd_rn(__fmul_rn(y, x), p4);
    y = __fadd_rn(__fmul_rn(y, x), p5);
    y = __fadd_rn(__fmul_rn(y, z), x);
    y = __fadd_rn(1.0f, y);

    int n = (int)fx;
    return __int_as_float(__float_as_int(y) + (n << 23));
}

__device__ __forceinline__ ull ffma2(ull a, ull b, ull c) {
    ull d;
    asm("fma.rn.f32x2 %0, %1, %2, %3;" : "=l"(d) : "l"(a), "l"(b), "l"(c));
    return d;
}
__device__ __forceinline__ ull add2(ull a, ull b) {
    ull d;
    asm("add.rn.f32x2 %0, %1, %2;" : "=l"(d) : "l"(a), "l"(b));
    return d;
}
__device__ __forceinline__ ull dup2(float w) {
    ull d; unsigned u = __float_as_uint(w);
    asm("mov.b64 %0, {%1, %1};" : "=l"(d) : "r"(u));
    return d;
}
__device__ __forceinline__ float2 unpack2(ull v) {
    float2 f;
    asm("mov.b64 {%0, %1}, %2;" : "=f"(f.x), "=f"(f.y) : "l"(v));
    return f;
}

// ALIF update, FMA-contracted (LLVM AllowFPOpFusion::Fast) — the verified
// bit-exact numeric contract from R9. DO NOT CHANGE.
__device__ __forceinline__ void alif_step(float h, float& m, float& b, float sold,
                                          float alpha, float oma, float ro, float omro,
                                          float& snew) {
    b = __fmaf_rn(ro, b, __fmul_rn(omro, sold));
    float Bth = __fmaf_rn(1.8f, b, 0.01f);
    float X = __fmaf_rn(m, alpha, __fmul_rn(oma, h));
    m = __fmaf_rn(-Bth, sold, X);
    snew = (__fsub_rn(m, Bth) > 0.0f) ? 1.0f : 0.0f;
}

// ---------------------------------------------------------------------------
// Tiled transpose of the 5 big weight matrices into g_wt [m][i][j].
// grid (16,16,5), block (32,32)
// ---------------------------------------------------------------------------
__global__ void transpose5_kernel(const float* __restrict__ w0,
                                  const float* __restrict__ w1,
                                  const float* __restrict__ w2,
                                  const float* __restrict__ w3,
                                  const float* __restrict__ w4) {
    __shared__ float tile[32][33];
    const float* src;
    switch (blockIdx.z) {
        case 0: src = w0; break;
        case 1: src = w1; break;
        case 2: src = w2; break;
        case 3: src = w3; break;
        default: src = w4; break;
    }
    int i0 = blockIdx.x * 32;   // column of original (input dim)
    int j0 = blockIdx.y * 32;   // row of original (output neuron)
    int tx = threadIdx.x, ty = threadIdx.y;
    tile[ty][tx] = src[(j0 + ty) * H + (i0 + tx)];
    __syncthreads();
    g_wt[(size_t)blockIdx.z * H * H + (size_t)(i0 + ty) * H + (j0 + tx)] = tile[tx][ty];
}

// ---------------------------------------------------------------------------
// Main persistent SRNN kernel, event-driven.
// One block = 4 samples, thread j = neuron j.
// Smem: 6 spike buffers [H][SPB] (double-buffered per layer) + 6 compacted
// fire-lists (ascending order => bit-exact FMA chain) + counts + warp counts.
// ---------------------------------------------------------------------------
extern __shared__ float smem[];

// event-driven matvec: acc over firing neurons only (ascending order)
__device__ __forceinline__ void event_matvec(
    const ushort_t* __restrict__ list, int cnt,
    const float* __restrict__ wt_base,      // g_wt + m*H*H + j
    const float* __restrict__ spk,          // [H][SPB]
    ull& acc0, ull& acc1)
{
#pragma unroll 4
    for (int k = 0; k < cnt; ++k) {
        int i = list[k];
        float w = __ldg(wt_base + (size_t)i * H);
        ulonglong2 sv = *(const ulonglong2*)(spk + i * SPB);
        ull wd = dup2(w);
        acc0 = ffma2(wd, sv.x, acc0);
        acc1 = ffma2(wd, sv.y, acc1);
    }
}

__global__ void __launch_bounds__(NTHR, 1) srnn_kernel(
    const float* __restrict__ x,
    const float* __restrict__ i2h1_w, const float* __restrict__ i2h1_b,
    const float* __restrict__ h2h1_b,
    const float* __restrict__ i2h2_b, const float* __restrict__ h2h2_b,
    const float* __restrict__ i2h3_b, const float* __restrict__ h2h3_b,
    const float* __restrict__ h2o_w,  const float* __restrict__ h2o_b,
    const float* __restrict__ tau_adp_h1, const float* __restrict__ tau_adp_h2,
    const float* __restrict__ tau_adp_h3,
    const float* __restrict__ tau_m_h1,   const float* __restrict__ tau_m_h2,
    const float* __restrict__ tau_m_h3,
    float* __restrict__ out)
{
    const int j    = threadIdx.x;
    const int warp = j >> 5, lane = j & 31;
    const unsigned lanemask_lt = (1u << lane) - 1u;
    const int smp0 = blockIdx.x * SPB;

    // smem carve-up
    float*    spk   = smem;                                   // 6 * H * SPB floats
    ushort_t* lists = (ushort_t*)(spk + 6 * H * SPB);         // 6 * H
    int*      cnts  = (int*)(lists + 6 * H);                  // 6
    int*      wcnt  = cnts + 6;                               // NWARP

    // buffer ids: layer l current = 2*l + cur, next = 2*l + (cur^1)
    int cur = 0;

    {
        float4 z = make_float4(0.f, 0.f, 0.f, 0.f);
#pragma unroll
        for (int b = 0; b < 6; ++b)
            *(float4*)(spk + b * H * SPB + j * SPB) = z;
        if (j < 6) cnts[j] = 0;
    }

    const float a1 = xla_cephes_expf(__fdiv_rn(-1.0f, tau_m_h1[j]));
    const float a2 = xla_cephes_expf(__fdiv_rn(-1.0f, tau_m_h2[j]));
    const float a3 = xla_cephes_expf(__fdiv_rn(-1.0f, tau_m_h3[j]));
    const float r1 = xla_cephes_expf(__fdiv_rn(-1.0f, tau_adp_h1[j]));
    const float r2 = xla_cephes_expf(__fdiv_rn(-1.0f, tau_adp_h2[j]));
    const float r3 = xla_cephes_expf(__fdiv_rn(-1.0f, tau_adp_h3[j]));
    const float oma1 = __fsub_rn(1.0f, a1), oma2 = __fsub_rn(1.0f, a2),
                oma3 = __fsub_rn(1.0f, a3);
    const float omr1 = __fsub_rn(1.0f, r1), omr2 = __fsub_rn(1.0f, r2),
                omr3 = __fsub_rn(1.0f, r3);

    const float bi1 = i2h1_b[j], bh1 = h2h1_b[j];
    const ull bi2d = dup2(i2h2_b[j]), bh2d = dup2(h2h2_b[j]);
    const ull bi3d = dup2(i2h3_b[j]), bh3d = dup2(h2h3_b[j]);

    float wi1[INW];
    {
        float4 wa = *(const float4*)(i2h1_w + j * INW);
        float4 wb = *(const float4*)(i2h1_w + j * INW + 4);
        wi1[0] = wa.x; wi1[1] = wa.y; wi1[2] = wa.z; wi1[3] = wa.w;
        wi1[4] = wb.x; wi1[5] = wb.y; wi1[6] = wb.z; wi1[7] = wb.w;
    }

    float m1[SPB], m2[SPB], m3[SPB], b1[SPB], b2[SPB], b3[SPB], c3[SPB];
#pragma unroll
    for (int s = 0; s < SPB; ++s) {
        m1[s] = m2[s] = m3[s] = 0.0f;
        b1[s] = b2[s] = b3[s] = 0.01f;
        c3[s] = 0.0f;
    }

    const float* wt_h2h1 = g_wt + 0 * H * H + j;
    const float* wt_i2h2 = g_wt + 1 * H * H + j;
    const float* wt_h2h2 = g_wt + 2 * H * H + j;
    const float* wt_i2h3 = g_wt + 3 * H * H + j;
    const float* wt_h2h3 = g_wt + 4 * H * H + j;

    __syncthreads();

    for (int t = 0; t < TSTEPS; ++t) {
        const int st = (t * INW < TSTEPS - INW) ? t * INW : (NPIX - INW);

        const int b1c = 0 + cur, b1n = 0 + (cur ^ 1);
        const int b2c = 2 + cur, b2n = 2 + (cur ^ 1);
        const int b3c = 4 + cur, b3n = 4 + (cur ^ 1);
        float* spk1c = spk + b1c * H * SPB;  float* spk1n = spk + b1n * H * SPB;
        float* spk2c = spk + b2c * H * SPB;  float* spk2n = spk + b2n * H * SPB;
        float* spk3c = spk + b3c * H * SPB;  float* spk3n = spk + b3n * H * SPB;

        // ================= layer 1 =================
        ull accH0 = 0ull, accH1 = 0ull;
        event_matvec(lists + b1c * H, cnts[b1c], wt_h2h1, spk1c, accH0, accH1);

        float snew[SPB];
        {
            const float* xb = x + (size_t)smp0 * NPIX + st;
            float4 so = *(float4*)(spk1c + j * SPB);
            float sold[SPB] = {so.x, so.y, so.z, so.w};
            ull accp[2] = {accH0, accH1};
#pragma unroll
            for (int s = 0; s < SPB; ++s) {
                float4 xa = *(const float4*)(xb + (size_t)s * NPIX);
                float4 xc = *(const float4*)(xb + (size_t)s * NPIX + 4);
                float dx = __fmaf_rn(xa.x, wi1[0], 0.0f);
                dx = __fmaf_rn(xa.y, wi1[1], dx);
                dx = __fmaf_rn(xa.z, wi1[2], dx);
                dx = __fmaf_rn(xa.w, wi1[3], dx);
                dx = __fmaf_rn(xc.x, wi1[4], dx);
                dx = __fmaf_rn(xc.y, wi1[5], dx);
                dx = __fmaf_rn(xc.z, wi1[6], dx);
                dx = __fmaf_rn(xc.w, wi1[7], dx);
                float2 dh2 = unpack2(accp[s >> 1]);
                float dh = (s & 1) ? dh2.y : dh2.x;
                float h = __fadd_rn(__fadd_rn(__fadd_rn(dx, bi1), dh), bh1);
                alif_step(h, m1[s], b1[s], sold[s], a1, oma1, r1, omr1, snew[s]);
            }
        }
        // store spikes + build fire-list for buffer b1n (ascending order)
        {
            *(float4*)(spk1n + j * SPB) = make_float4(snew[0], snew[1], snew[2], snew[3]);
            bool any = (snew[0] + snew[1] + snew[2] + snew[3]) > 0.0f;
            unsigned mask = __ballot_sync(0xffffffffu, any);
            if (lane == 0) wcnt[warp] = __popc(mask);
            __syncthreads();
            int base = 0, total = 0;
#pragma unroll
            for (int w = 0; w < NWARP; ++w) {
                int c = wcnt[w];
                if (w < warp) base += c;
                total += c;
            }
            if (any) lists[b1n * H + base + __popc(mask & lanemask_lt)] = (ushort_t)j;
            if (j == 0) cnts[b1n] = total;
            __syncthreads();
        }

        // ================= layer 2 =================
        ull accI0 = 0ull, accI1 = 0ull;
        accH0 = 0ull; accH1 = 0ull;
        event_matvec(lists + b1n * H, cnts[b1n], wt_i2h2, spk1n, accI0, accI1);
        event_matvec(lists + b2c * H, cnts[b2c], wt_h2h2, spk2c, accH0, accH1);
        {
            float4 so = *(float4*)(spk2c + j * SPB);
            float sold[SPB] = {so.x, so.y, so.z, so.w};
            ull accIp[2] = {accI0, accI1};
            ull accHp[2] = {accH0, accH1};
#pragma unroll
            for (int q = 0; q < 2; ++q) {
                ull h2v = add2(add2(add2(accIp[q], bi2d), accHp[q]), bh2d);
                float2 hv = unpack2(h2v);
                alif_step(hv.x, m2[2*q],   b2[2*q],   sold[2*q],   a2, oma2, r2, omr2, snew[2*q]);
                alif_step(hv.y, m2[2*q+1], b2[2*q+1], sold[2*q+1], a2, oma2, r2, omr2, snew[2*q+1]);
            }
        }
        {
            *(float4*)(spk2n + j * SPB) = make_float4(snew[0], snew[1], snew[2], snew[3]);
            bool any = (snew[0] + snew[1] + snew[2] + snew[3]) > 0.0f;
            unsigned mask = __ballot_sync(0xffffffffu, any);
            if (lane == 0) wcnt[warp] = __popc(mask);
            __syncthreads();
            int base = 0, total = 0;
#pragma unroll
            for (int w = 0; w < NWARP; ++w) {
                int c = wcnt[w];
                if (w < warp) base += c;
                total += c;
            }
            if (any) lists[b2n * H + base + __popc(mask & lanemask_lt)] = (ushort_t)j;
            if (j == 0) cnts[b2n] = total;
            __syncthreads();
        }

        // ================= layer 3 =================
        accI0 = 0ull; accI1 = 0ull;
        accH0 = 0ull; accH1 = 0ull;
        event_matvec(lists + b2n * H, cnts[b2n], wt_i2h3, spk2n, accI0, accI1);
        event_matvec(lists + b3c * H, cnts[b3c], wt_h2h3, spk3c, accH0, accH1);
        {
            float4 so = *(float4*)(spk3c + j * SPB);
            float sold[SPB] = {so.x, so.y, so.z, so.w};
            ull accIp[2] = {accI0, accI1};
            ull accHp[2] = {accH0, accH1};
#pragma unroll
            for (int q = 0; q < 2; ++q) {
                ull h2v = add2(add2(add2(accIp[q], bi3d), accHp[q]), bh3d);
                float2 hv = unpack2(h2v);
                alif_step(hv.x, m3[2*q],   b3[2*q],   sold[2*q],   a3, oma3, r3, omr3, snew[2*q]);
                alif_step(hv.y, m3[2*q+1], b3[2*q+1], sold[2*q+1], a3, oma3, r3, omr3, snew[2*q+1]);
            }
        }
        {
            *(float4*)(spk3n + j * SPB) = make_float4(snew[0], snew[1], snew[2], snew[3]);
            bool any = (snew[0] + snew[1] + snew[2] + snew[3]) > 0.0f;
            unsigned mask = __ballot_sync(0xffffffffu, any);
            if (lane == 0) wcnt[warp] = __popc(mask);
            __syncthreads();
            int base = 0, total = 0;
#pragma unroll
            for (int w = 0; w < NWARP; ++w) {
                int c = wcnt[w];
                if (w < warp) base += c;
                total += c;
            }
            if (any) lists[b3n * H + base + __popc(mask & lanemask_lt)] = (ushort_t)j;
            if (j == 0) cnts[b3n] = total;
#pragma unroll
            for (int s = 0; s < SPB; ++s) c3[s] += snew[s];
            __syncthreads();
        }

        cur ^= 1;
    }

    // ======== output: out[smp][o] = (sum_j c3[smp][j]*W[o][j]) / T + b[o] ========
    __syncthreads();
#pragma unroll
    for (int s = 0; s < SPB; ++s) spk[s * H + j] = c3[s];
    __syncthreads();

    for (int pair = warp; pair < SPB * OUTN; pair += NWARP) {
        int s = pair / OUTN, o = pair % OUTN;
        float sum = 0.0f;
        for (int jj = lane; jj < H; jj += 32)
            sum += spk[s * H + jj] * __ldg(h2o_w + o * H + jj);
#pragma unroll
        for (int off = 16; off > 0; off >>= 1)
            sum += __shfl_down_sync(0xffffffffu, sum, off);
        if (lane == 0)
            out[(size_t)(smp0 + s) * OUTN + o] = sum / (float)TSTEPS + h2o_b[o];
    }
}

// ---------------------------------------------------------------------------
extern "C" void kernel_launch(void* const* d_in, const int* in_sizes, int n_in,
                              void* d_out, int out_size) {
    (void)in_sizes; (void)n_in; (void)out_size;
    const float* x          = (const float*)d_in[0];
    const float* i2h1_w     = (const float*)d_in[1];
    const float* i2h1_b     = (const float*)d_in[2];
    const float* h2h1_w     = (const float*)d_in[3];
    const float* h2h1_b     = (const float*)d_in[4];
    const float* i2h2_w     = (const float*)d_in[5];
    const float* i2h2_b     = (const float*)d_in[6];
    const float* h2h2_w     = (const float*)d_in[7];
    const float* h2h2_b     = (const float*)d_in[8];
    const float* i2h3_w     = (const float*)d_in[9];
    const float* i2h3_b     = (const float*)d_in[10];
    const float* h2h3_w     = (const float*)d_in[11];
    const float* h2h3_b     = (const float*)d_in[12];
    const float* h2o_w      = (const float*)d_in[13];
    const float* h2o_b      = (const float*)d_in[14];
    const float* tau_adp_h1 = (const float*)d_in[15];
    const float* tau_adp_h2 = (const float*)d_in[16];
    const float* tau_adp_h3 = (const float*)d_in[17];
    const float* tau_m_h1   = (const float*)d_in[18];
    const float* tau_m_h2   = (const float*)d_in[19];
    const float* tau_m_h3   = (const float*)d_in[20];
    float* out = (float*)d_out;

    transpose5_kernel<<<dim3(16, 16, 5), dim3(32, 32)>>>(h2h1_w, i2h2_w, h2h2_w,
                                                         i2h3_w, h2h3_w);

    // smem: 6 spike bufs (48KB) + 6 lists (6KB) + counts
    const size_t smem_bytes = 6 * H * SPB * sizeof(float)
                            + 6 * H * sizeof(unsigned short)
                            + (6 + NTHR / 32) * sizeof(int);
    static int attr_set = 0;
    if (!attr_set) {
        cudaFuncSetAttribute(srnn_kernel,
                             cudaFuncAttributeMaxDynamicSharedMemorySize,
                             (int)smem_bytes);
        attr_set = 1;
    }
    srnn_kernel<<<NBLK, NTHR, smem_bytes>>>(
        x, i2h1_w, i2h1_b, h2h1_b, i2h2_b, h2h2_b, i2h3_b, h2h3_b,
        h2o_w, h2o_b, tau_adp_h1, tau_adp_h2, tau_adp_h3,
        tau_m_h1, tau_m_h2, tau_m_h3, out);
}

// round 13
// speedup vs baseline: 3.8534x; 1.1798x over previous
#include <cuda_runtime.h>

#define H      512
#define TSTEPS 98
#define INW    8
#define NPIX   784
#define OUTN   10
#define NBATCH 512
#define SPB    4                 // samples per block
#define NBLK   (NBATCH / SPB)    // 128 blocks
#define NTHR   512               // thread j owns neuron j in all 3 layers
#define NWARP  (NTHR / 32)       // 16

// Transposed weights [matrix][i][j]:
// 0: h2h1, 1: i2h2, 2: h2h2, 3: i2h3, 4: h2h3
__device__ float g_wt[5 * H * H];

typedef unsigned long long ull;
typedef unsigned short ushort_t;

// ---------------------------------------------------------------------------
// Cephes/glibc-class expf (verified bit-identical to reference on all taus).
// ---------------------------------------------------------------------------
__device__ __forceinline__ float xla_cephes_expf(float x) {
    const float LOG2EF = 1.44269504088896341f;
    const float C1 = 0.693359375f;
    const float C2 = -2.12194440e-4f;
    const float p0 = 1.9875691500E-4f;
    const float p1 = 1.3981999507E-3f;
    const float p2 = 8.3334519073E-3f;
    const float p3 = 4.1665795894E-2f;
    const float p4 = 1.6666665459E-1f;
    const float p5 = 5.0000001201E-1f;

    x = fminf(x, 88.3762626647950f);
    x = fmaxf(x, -88.3762626647949f);

    float fx = floorf(__fadd_rn(__fmul_rn(x, LOG2EF), 0.5f));
    x = __fsub_rn(x, __fmul_rn(fx, C1));
    x = __fsub_rn(x, __fmul_rn(fx, C2));

    float z = __fmul_rn(x, x);
    float y = p0;
    y = __fadd_rn(__fmul_rn(y, x), p1);
    y = __fadd_rn(__fmul_rn(y, x), p2);
    y = __fadd_rn(__fmul_rn(y, x), p3);
    y = __fadd_rn(__fmul_rn(y, x), p4);
    y = __fadd_rn(__fmul_rn(y, x), p5);
    y = __fadd_rn(__fmul_rn(y, z), x);
    y = __fadd_rn(1.0f, y);

    int n = (int)fx;
    return __int_as_float(__float_as_int(y) + (n << 23));
}

__device__ __forceinline__ ull ffma2(ull a, ull b, ull c) {
    ull d;
    asm("fma.rn.f32x2 %0, %1, %2, %3;" : "=l"(d) : "l"(a), "l"(b), "l"(c));
    return d;
}
__device__ __forceinline__ ull add2(ull a, ull b) {
    ull d;
    asm("add.rn.f32x2 %0, %1, %2;" : "=l"(d) : "l"(a), "l"(b));
    return d;
}
__device__ __forceinline__ ull dup2(float w) {
    ull d; unsigned u = __float_as_uint(w);
    asm("mov.b64 %0, {%1, %1};" : "=l"(d) : "r"(u));
    return d;
}
__device__ __forceinline__ float2 unpack2(ull v) {
    float2 f;
    asm("mov.b64 {%0, %1}, %2;" : "=f"(f.x), "=f"(f.y) : "l"(v));
    return f;
}

// ALIF update, FMA-contracted (LLVM AllowFPOpFusion::Fast) — the verified
// bit-exact numeric contract from R9. DO NOT CHANGE.
__device__ __forceinline__ void alif_step(float h, float& m, float& b, float sold,
                                          float alpha, float oma, float ro, float omro,
                                          float& snew) {
    b = __fmaf_rn(ro, b, __fmul_rn(omro, sold));
    float Bth = __fmaf_rn(1.8f, b, 0.01f);
    float X = __fmaf_rn(m, alpha, __fmul_rn(oma, h));
    m = __fmaf_rn(-Bth, sold, X);
    snew = (__fsub_rn(m, Bth) > 0.0f) ? 1.0f : 0.0f;
}

// ---------------------------------------------------------------------------
// Tiled transpose of the 5 big weight matrices into g_wt [m][i][j].
// grid (16,16,5), block (32,32)
// ---------------------------------------------------------------------------
__global__ void transpose5_kernel(const float* __restrict__ w0,
                                  const float* __restrict__ w1,
                                  const float* __restrict__ w2,
                                  const float* __restrict__ w3,
                                  const float* __restrict__ w4) {
    __shared__ float tile[32][33];
    const float* src;
    switch (blockIdx.z) {
        case 0: src = w0; break;
        case 1: src = w1; break;
        case 2: src = w2; break;
        case 3: src = w3; break;
        default: src = w4; break;
    }
    int i0 = blockIdx.x * 32;   // column of original (input dim)
    int j0 = blockIdx.y * 32;   // row of original (output neuron)
    int tx = threadIdx.x, ty = threadIdx.y;
    tile[ty][tx] = src[(j0 + ty) * H + (i0 + tx)];
    __syncthreads();
    g_wt[(size_t)blockIdx.z * H * H + (size_t)(i0 + ty) * H + (j0 + tx)] = tile[tx][ty];
}

// ---------------------------------------------------------------------------
// Event-driven matvec, software-pipelined in tiles of 8:
//   1) two LDS.64 fetch 8 packed ushort indices (masked &0x1FF -> in-bounds
//      even for tail garbage),
//   2) 8 INDEPENDENT predicated weight LDGs (out-of-range -> w = 0, which is
//      an exact FMA no-op),
//   3) sequential FFMA2 chain in ascending-k order  => bit-exact vs dense.
// ---------------------------------------------------------------------------
__device__ __forceinline__ void event_matvec(
    const ushort_t* __restrict__ list, int cnt,
    const float* __restrict__ wt_base,      // g_wt + m*H*H + j
    const float* __restrict__ spk,          // [H][SPB]
    ull& acc0, ull& acc1)
{
    for (int k0 = 0; k0 < cnt; k0 += 8) {
        const ull* lp = (const ull*)(list + k0);   // 16B-aligned (k0 % 8 == 0)
        ull e0 = lp[0], e1 = lp[1];
        int ii[8];
        ii[0] = (int)(e0 >>  0) & 0x1FF;
        ii[1] = (int)(e0 >> 16) & 0x1FF;
        ii[2] = (int)(e0 >> 32) & 0x1FF;
        ii[3] = (int)(e0 >> 48) & 0x1FF;
        ii[4] = (int)(e1 >>  0) & 0x1FF;
        ii[5] = (int)(e1 >> 16) & 0x1FF;
        ii[6] = (int)(e1 >> 32) & 0x1FF;
        ii[7] = (int)(e1 >> 48) & 0x1FF;
        float w[8];
#pragma unroll
        for (int u = 0; u < 8; ++u)
            w[u] = (k0 + u < cnt) ? __ldg(wt_base + (size_t)ii[u] * H) : 0.0f;
#pragma unroll
        for (int u = 0; u < 8; ++u) {
            ulonglong2 sv = *(const ulonglong2*)(spk + ii[u] * SPB);
            ull wd = dup2(w[u]);
            acc0 = ffma2(wd, sv.x, acc0);
            acc1 = ffma2(wd, sv.y, acc1);
        }
    }
}

// ---------------------------------------------------------------------------
// Main persistent SRNN kernel, event-driven.
// One block = 4 samples, thread j = neuron j.
// ---------------------------------------------------------------------------
extern __shared__ float smem[];

__global__ void __launch_bounds__(NTHR, 1) srnn_kernel(
    const float* __restrict__ x,
    const float* __restrict__ i2h1_w, const float* __restrict__ i2h1_b,
    const float* __restrict__ h2h1_b,
    const float* __restrict__ i2h2_b, const float* __restrict__ h2h2_b,
    const float* __restrict__ i2h3_b, const float* __restrict__ h2h3_b,
    const float* __restrict__ h2o_w,  const float* __restrict__ h2o_b,
    const float* __restrict__ tau_adp_h1, const float* __restrict__ tau_adp_h2,
    const float* __restrict__ tau_adp_h3,
    const float* __restrict__ tau_m_h1,   const float* __restrict__ tau_m_h2,
    const float* __restrict__ tau_m_h3,
    float* __restrict__ out)
{
    const int j    = threadIdx.x;
    const int warp = j >> 5, lane = j & 31;
    const unsigned lanemask_lt = (1u << lane) - 1u;
    const int smp0 = blockIdx.x * SPB;

    // smem carve-up
    float*    spk   = smem;                                   // 6 * H * SPB floats
    ushort_t* lists = (ushort_t*)(spk + 6 * H * SPB);         // 6 * H
    int*      cnts  = (int*)(lists + 6 * H);                  // 6
    int*      wcnt  = cnts + 6;                               // NWARP

    int cur = 0;

    {
        float4 z = make_float4(0.f, 0.f, 0.f, 0.f);
#pragma unroll
        for (int b = 0; b < 6; ++b)
            *(float4*)(spk + b * H * SPB + j * SPB) = z;
        if (j < 6) cnts[j] = 0;
    }

    const float a1 = xla_cephes_expf(__fdiv_rn(-1.0f, tau_m_h1[j]));
    const float a2 = xla_cephes_expf(__fdiv_rn(-1.0f, tau_m_h2[j]));
    const float a3 = xla_cephes_expf(__fdiv_rn(-1.0f, tau_m_h3[j]));
    const float r1 = xla_cephes_expf(__fdiv_rn(-1.0f, tau_adp_h1[j]));
    const float r2 = xla_cephes_expf(__fdiv_rn(-1.0f, tau_adp_h2[j]));
    const float r3 = xla_cephes_expf(__fdiv_rn(-1.0f, tau_adp_h3[j]));
    const float oma1 = __fsub_rn(1.0f, a1), oma2 = __fsub_rn(1.0f, a2),
                oma3 = __fsub_rn(1.0f, a3);
    const float omr1 = __fsub_rn(1.0f, r1), omr2 = __fsub_rn(1.0f, r2),
                omr3 = __fsub_rn(1.0f, r3);

    const float bi1 = i2h1_b[j], bh1 = h2h1_b[j];
    const ull bi2d = dup2(i2h2_b[j]), bh2d = dup2(h2h2_b[j]);
    const ull bi3d = dup2(i2h3_b[j]), bh3d = dup2(h2h3_b[j]);

    float wi1[INW];
    {
        float4 wa = *(const float4*)(i2h1_w + j * INW);
        float4 wb = *(const float4*)(i2h1_w + j * INW + 4);
        wi1[0] = wa.x; wi1[1] = wa.y; wi1[2] = wa.z; wi1[3] = wa.w;
        wi1[4] = wb.x; wi1[5] = wb.y; wi1[6] = wb.z; wi1[7] = wb.w;
    }

    float m1[SPB], m2[SPB], m3[SPB], b1[SPB], b2[SPB], b3[SPB], c3[SPB];
#pragma unroll
    for (int s = 0; s < SPB; ++s) {
        m1[s] = m2[s] = m3[s] = 0.0f;
        b1[s] = b2[s] = b3[s] = 0.01f;
        c3[s] = 0.0f;
    }

    const float* wt_h2h1 = g_wt + 0 * H * H + j;
    const float* wt_i2h2 = g_wt + 1 * H * H + j;
    const float* wt_h2h2 = g_wt + 2 * H * H + j;
    const float* wt_i2h3 = g_wt + 3 * H * H + j;
    const float* wt_h2h3 = g_wt + 4 * H * H + j;

    __syncthreads();

    for (int t = 0; t < TSTEPS; ++t) {
        const int st = (t * INW < TSTEPS - INW) ? t * INW : (NPIX - INW);

        const int b1c = 0 + cur, b1n = 0 + (cur ^ 1);
        const int b2c = 2 + cur, b2n = 2 + (cur ^ 1);
        const int b3c = 4 + cur, b3n = 4 + (cur ^ 1);
        float* spk1c = spk + b1c * H * SPB;  float* spk1n = spk + b1n * H * SPB;
        float* spk2c = spk + b2c * H * SPB;  float* spk2n = spk + b2n * H * SPB;
        float* spk3c = spk + b3c * H * SPB;  float* spk3n = spk + b3n * H * SPB;

        // ================= layer 1 =================
        ull accH0 = 0ull, accH1 = 0ull;
        event_matvec(lists + b1c * H, cnts[b1c], wt_h2h1, spk1c, accH0, accH1);

        float snew[SPB];
        {
            const float* xb = x + (size_t)smp0 * NPIX + st;
            float4 so = *(float4*)(spk1c + j * SPB);
            float sold[SPB] = {so.x, so.y, so.z, so.w};
            ull accp[2] = {accH0, accH1};
#pragma unroll
            for (int s = 0; s < SPB; ++s) {
                float4 xa = *(const float4*)(xb + (size_t)s * NPIX);
                float4 xc = *(const float4*)(xb + (size_t)s * NPIX + 4);
                float dx = __fmaf_rn(xa.x, wi1[0], 0.0f);
                dx = __fmaf_rn(xa.y, wi1[1], dx);
                dx = __fmaf_rn(xa.z, wi1[2], dx);
                dx = __fmaf_rn(xa.w, wi1[3], dx);
                dx = __fmaf_rn(xc.x, wi1[4], dx);
                dx = __fmaf_rn(xc.y, wi1[5], dx);
                dx = __fmaf_rn(xc.z, wi1[6], dx);
                dx = __fmaf_rn(xc.w, wi1[7], dx);
                float2 dh2 = unpack2(accp[s >> 1]);
                float dh = (s & 1) ? dh2.y : dh2.x;
                float h = __fadd_rn(__fadd_rn(__fadd_rn(dx, bi1), dh), bh1);
                alif_step(h, m1[s], b1[s], sold[s], a1, oma1, r1, omr1, snew[s]);
            }
        }
        {
            *(float4*)(spk1n + j * SPB) = make_float4(snew[0], snew[1], snew[2], snew[3]);
            bool any = (snew[0] + snew[1] + snew[2] + snew[3]) > 0.0f;
            unsigned mask = __ballot_sync(0xffffffffu, any);
            if (lane == 0) wcnt[warp] = __popc(mask);
            __syncthreads();
            int base = 0, total = 0;
#pragma unroll
            for (int w = 0; w < NWARP; ++w) {
                int c = wcnt[w];
                if (w < warp) base += c;
                total += c;
            }
            if (any) lists[b1n * H + base + __popc(mask & lanemask_lt)] = (ushort_t)j;
            if (j == 0) cnts[b1n] = total;
            __syncthreads();
        }

        // ================= layer 2 =================
        ull accI0 = 0ull, accI1 = 0ull;
        accH0 = 0ull; accH1 = 0ull;
        event_matvec(lists + b1n * H, cnts[b1n], wt_i2h2, spk1n, accI0, accI1);
        event_matvec(lists + b2c * H, cnts[b2c], wt_h2h2, spk2c, accH0, accH1);
        {
            float4 so = *(float4*)(spk2c + j * SPB);
            float sold[SPB] = {so.x, so.y, so.z, so.w};
            ull accIp[2] = {accI0, accI1};
            ull accHp[2] = {accH0, accH1};
#pragma unroll
            for (int q = 0; q < 2; ++q) {
                ull h2v = add2(add2(add2(accIp[q], bi2d), accHp[q]), bh2d);
                float2 hv = unpack2(h2v);
                alif_step(hv.x, m2[2*q],   b2[2*q],   sold[2*q],   a2, oma2, r2, omr2, snew[2*q]);
                alif_step(hv.y, m2[2*q+1], b2[2*q+1], sold[2*q+1], a2, oma2, r2, omr2, snew[2*q+1]);
            }
        }
        {
            *(float4*)(spk2n + j * SPB) = make_float4(snew[0], snew[1], snew[2], snew[3]);
            bool any = (snew[0] + snew[1] + snew[2] + snew[3]) > 0.0f;
            unsigned mask = __ballot_sync(0xffffffffu, any);
            if (lane == 0) wcnt[warp] = __popc(mask);
            __syncthreads();
            int base = 0, total = 0;
#pragma unroll
            for (int w = 0; w < NWARP; ++w) {
                int c = wcnt[w];
                if (w < warp) base += c;
                total += c;
            }
            if (any) lists[b2n * H + base + __popc(mask & lanemask_lt)] = (ushort_t)j;
            if (j == 0) cnts[b2n] = total;
            __syncthreads();
        }

        // ================= layer 3 =================
        accI0 = 0ull; accI1 = 0ull;
        accH0 = 0ull; accH1 = 0ull;
        event_matvec(lists + b2n * H, cnts[b2n], wt_i2h3, spk2n, accI0, accI1);
        event_matvec(lists + b3c * H, cnts[b3c], wt_h2h3, spk3c, accH0, accH1);
        {
            float4 so = *(float4*)(spk3c + j * SPB);
            float sold[SPB] = {so.x, so.y, so.z, so.w};
            ull accIp[2] = {accI0, accI1};
            ull accHp[2] = {accH0, accH1};
#pragma unroll
            for (int q = 0; q < 2; ++q) {
                ull h2v = add2(add2(add2(accIp[q], bi3d), accHp[q]), bh3d);
                float2 hv = unpack2(h2v);
                alif_step(hv.x, m3[2*q],   b3[2*q],   sold[2*q],   a3, oma3, r3, omr3, snew[2*q]);
                alif_step(hv.y, m3[2*q+1], b3[2*q+1], sold[2*q+1], a3, oma3, r3, omr3, snew[2*q+1]);
            }
        }
        {
            *(float4*)(spk3n + j * SPB) = make_float4(snew[0], snew[1], snew[2], snew[3]);
            bool any = (snew[0] + snew[1] + snew[2] + snew[3]) > 0.0f;
            unsigned mask = __ballot_sync(0xffffffffu, any);
            if (lane == 0) wcnt[warp] = __popc(mask);
            __syncthreads();
            int base = 0, total = 0;
#pragma unroll
            for (int w = 0; w < NWARP; ++w) {
                int c = wcnt[w];
                if (w < warp) base += c;
                total += c;
            }
            if (any) lists[b3n * H + base + __popc(mask & lanemask_lt)] = (ushort_t)j;
            if (j == 0) cnts[b3n] = total;
#pragma unroll
            for (int s = 0; s < SPB; ++s) c3[s] += snew[s];
            __syncthreads();
        }

        cur ^= 1;
    }

    // ======== output: out[smp][o] = (sum_j c3[smp][j]*W[o][j]) / T + b[o] ========
    __syncthreads();
#pragma unroll
    for (int s = 0; s < SPB; ++s) spk[s * H + j] = c3[s];
    __syncthreads();

    for (int pair = warp; pair < SPB * OUTN; pair += NWARP) {
        int s = pair / OUTN, o = pair % OUTN;
        float sum = 0.0f;
        for (int jj = lane; jj < H; jj += 32)
            sum += spk[s * H + jj] * __ldg(h2o_w + o * H + jj);
#pragma unroll
        for (int off = 16; off > 0; off >>= 1)
            sum += __shfl_down_sync(0xffffffffu, sum, off);
        if (lane == 0)
            out[(size_t)(smp0 + s) * OUTN + o] = sum / (float)TSTEPS + h2o_b[o];
    }
}

// ---------------------------------------------------------------------------
extern "C" void kernel_launch(void* const* d_in, const int* in_sizes, int n_in,
                              void* d_out, int out_size) {
    (void)in_sizes; (void)n_in; (void)out_size;
    const float* x          = (const float*)d_in[0];
    const float* i2h1_w     = (const float*)d_in[1];
    const float* i2h1_b     = (const float*)d_in[2];
    const float* h2h1_w     = (const float*)d_in[3];
    const float* h2h1_b     = (const float*)d_in[4];
    const float* i2h2_w     = (const float*)d_in[5];
    const float* i2h2_b     = (const float*)d_in[6];
    const float* h2h2_w     = (const float*)d_in[7];
    const float* h2h2_b     = (const float*)d_in[8];
    const float* i2h3_w     = (const float*)d_in[9];
    const float* i2h3_b     = (const float*)d_in[10];
    const float* h2h3_w     = (const float*)d_in[11];
    const float* h2h3_b     = (const float*)d_in[12];
    const float* h2o_w      = (const float*)d_in[13];
    const float* h2o_b      = (const float*)d_in[14];
    const float* tau_adp_h1 = (const float*)d_in[15];
    const float* tau_adp_h2 = (const float*)d_in[16];
    const float* tau_adp_h3 = (const float*)d_in[17];
    const float* tau_m_h1   = (const float*)d_in[18];
    const float* tau_m_h2   = (const float*)d_in[19];
    const float* tau_m_h3   = (const float*)d_in[20];
    float* out = (float*)d_out;

    transpose5_kernel<<<dim3(16, 16, 5), dim3(32, 32)>>>(h2h1_w, i2h2_w, h2h2_w,
                                                         i2h3_w, h2h3_w);

    const size_t smem_bytes = 6 * H * SPB * sizeof(float)
                            + 6 * H * sizeof(unsigned short)
                            + (6 + NTHR / 32) * sizeof(int);
    static int attr_set = 0;
    if (!attr_set) {
        cudaFuncSetAttribute(srnn_kernel,
                             cudaFuncAttributeMaxDynamicSharedMemorySize,
                             (int)smem_bytes);
        attr_set = 1;
    }
    srnn_kernel<<<NBLK, NTHR, smem_bytes>>>(
        x, i2h1_w, i2h1_b, h2h1_b, i2h2_b, h2h2_b, i2h3_b, h2h3_b,
        h2o_w, h2o_b, tau_adp_h1, tau_adp_h2, tau_adp_h3,
        tau_m_h1, tau_m_h2, tau_m_h3, out);
}

// round 14
// speedup vs baseline: 4.8355x; 1.2549x over previous
#include <cuda_runtime.h>

#define H      512
#define HPAD   8                 // zero weight rows per matrix (for list padding)
#define TSTEPS 98
#define INW    8
#define NPIX   784
#define OUTN   10
#define NBATCH 512
#define SPB    4                 // samples per block
#define NBLK   (NBATCH / SPB)    // 128 blocks
#define NTHR   512               // thread j owns neuron j in all 3 layers
#define NWARP  (NTHR / 32)       // 16
#define MATF   ((H + HPAD) * H)  // floats per matrix in g_wt

// Transposed weights [matrix][i][j], i in [0, H+HPAD), rows >= H are ZERO:
// 0: h2h1, 1: i2h2, 2: h2h2, 3: i2h3, 4: h2h3
__device__ float g_wt[5 * MATF];

typedef unsigned long long ull;

// ---------------------------------------------------------------------------
// Cephes/glibc-class expf (verified bit-identical to reference on all taus).
// ---------------------------------------------------------------------------
__device__ __forceinline__ float xla_cephes_expf(float x) {
    const float LOG2EF = 1.44269504088896341f;
    const float C1 = 0.693359375f;
    const float C2 = -2.12194440e-4f;
    const float p0 = 1.9875691500E-4f;
    const float p1 = 1.3981999507E-3f;
    const float p2 = 8.3334519073E-3f;
    const float p3 = 4.1665795894E-2f;
    const float p4 = 1.6666665459E-1f;
    const float p5 = 5.0000001201E-1f;

    x = fminf(x, 88.3762626647950f);
    x = fmaxf(x, -88.3762626647949f);

    float fx = floorf(__fadd_rn(__fmul_rn(x, LOG2EF), 0.5f));
    x = __fsub_rn(x, __fmul_rn(fx, C1));
    x = __fsub_rn(x, __fmul_rn(fx, C2));

    float z = __fmul_rn(x, x);
    float y = p0;
    y = __fadd_rn(__fmul_rn(y, x), p1);
    y = __fadd_rn(__fmul_rn(y, x), p2);
    y = __fadd_rn(__fmul_rn(y, x), p3);
    y = __fadd_rn(__fmul_rn(y, x), p4);
    y = __fadd_rn(__fmul_rn(y, x), p5);
    y = __fadd_rn(__fmul_rn(y, z), x);
    y = __fadd_rn(1.0f, y);

    int n = (int)fx;
    return __int_as_float(__float_as_int(y) + (n << 23));
}

__device__ __forceinline__ ull ffma2(ull a, ull b, ull c) {
    ull d;
    asm("fma.rn.f32x2 %0, %1, %2, %3;" : "=l"(d) : "l"(a), "l"(b), "l"(c));
    return d;
}
__device__ __forceinline__ ull add2(ull a, ull b) {
    ull d;
    asm("add.rn.f32x2 %0, %1, %2;" : "=l"(d) : "l"(a), "l"(b));
    return d;
}
__device__ __forceinline__ ull dup2(float w) {
    ull d; unsigned u = __float_as_uint(w);
    asm("mov.b64 %0, {%1, %1};" : "=l"(d) : "r"(u));
    return d;
}
__device__ __forceinline__ float2 unpack2(ull v) {
    float2 f;
    asm("mov.b64 {%0, %1}, %2;" : "=f"(f.x), "=f"(f.y) : "l"(v));
    return f;
}

// ALIF update, FMA-contracted (LLVM AllowFPOpFusion::Fast) — the verified
// bit-exact numeric contract from R9. DO NOT CHANGE.
__device__ __forceinline__ void alif_step(float h, float& m, float& b, float sold,
                                          float alpha, float oma, float ro, float omro,
                                          float& snew) {
    b = __fmaf_rn(ro, b, __fmul_rn(omro, sold));
    float Bth = __fmaf_rn(1.8f, b, 0.01f);
    float X = __fmaf_rn(m, alpha, __fmul_rn(oma, h));
    m = __fmaf_rn(-Bth, sold, X);
    snew = (__fsub_rn(m, Bth) > 0.0f) ? 1.0f : 0.0f;
}

// ---------------------------------------------------------------------------
// Tiled transpose into padded layout + zero the pad rows.
// grid (16,16,5), block (32,32)
// ---------------------------------------------------------------------------
__global__ void transpose5_kernel(const float* __restrict__ w0,
                                  const float* __restrict__ w1,
                                  const float* __restrict__ w2,
                                  const float* __restrict__ w3,
                                  const float* __restrict__ w4) {
    __shared__ float tile[32][33];
    const float* src;
    switch (blockIdx.z) {
        case 0: src = w0; break;
        case 1: src = w1; break;
        case 2: src = w2; break;
        case 3: src = w3; break;
        default: src = w4; break;
    }
    int i0 = blockIdx.x * 32;   // column of original (input dim)
    int j0 = blockIdx.y * 32;   // row of original (output neuron)
    int tx = threadIdx.x, ty = threadIdx.y;
    tile[ty][tx] = src[(j0 + ty) * H + (i0 + tx)];
    __syncthreads();
    g_wt[(size_t)blockIdx.z * MATF + (size_t)(i0 + ty) * H + (j0 + tx)] = tile[tx][ty];
    // zero pad rows (done redundantly by the i0==0 block slice)
    if (blockIdx.x == 0 && ty < HPAD) {
        int jz = blockIdx.y * 32 + tx;
        g_wt[(size_t)blockIdx.z * MATF + (size_t)(H + ty) * H + jz] = 0.0f;
    }
}

// ---------------------------------------------------------------------------
// Event-driven matvec over a padded offset list (cnt % 8 == 0).
// List entries are pre-scaled: v = i*16 = spike byte offset;
// weight byte offset = v << 7.  Pad entries have v = H*16 -> w = 0 (zero
// rows in g_wt) and a finite spike word -> fma(0, finite, acc) == acc exactly.
// Real entries ascending => FMA chain bit-exact vs dense.
// ---------------------------------------------------------------------------
__device__ __forceinline__ void event_matvec(
    const unsigned* __restrict__ list, int cnt,
    const char* __restrict__ wt_base,       // (char*)(g_wt + m*MATF + j)
    const char* __restrict__ spk_base,      // (char*)spk_buffer
    ull& acc0, ull& acc1)
{
    for (int k0 = 0; k0 < cnt; k0 += 8) {
        uint4 va = *(const uint4*)(list + k0);
        uint4 vb = *(const uint4*)(list + k0 + 4);
        unsigned vv[8] = {va.x, va.y, va.z, va.w, vb.x, vb.y, vb.z, vb.w};
        float w[8];
#pragma unroll
        for (int u = 0; u < 8; ++u)
            w[u] = __ldg((const float*)(wt_base + ((size_t)vv[u] << 7)));
#pragma unroll
        for (int u = 0; u < 8; ++u) {
            ulonglong2 sv = *(const ulonglong2*)(spk_base + vv[u]);
            ull wd = dup2(w[u]);
            acc0 = ffma2(wd, sv.x, acc0);
            acc1 = ffma2(wd, sv.y, acc1);
        }
    }
}

// ---------------------------------------------------------------------------
// Main persistent SRNN kernel, event-driven.
// One block = 4 samples, thread j = neuron j.
// smem: 6 spike bufs [H][SPB] + 16-float zero pad + 6 uint32 lists + counts.
// ---------------------------------------------------------------------------
extern __shared__ float smem[];

__global__ void __launch_bounds__(NTHR, 1) srnn_kernel(
    const float* __restrict__ x,
    const float* __restrict__ i2h1_w, const float* __restrict__ i2h1_b,
    const float* __restrict__ h2h1_b,
    const float* __restrict__ i2h2_b, const float* __restrict__ h2h2_b,
    const float* __restrict__ i2h3_b, const float* __restrict__ h2h3_b,
    const float* __restrict__ h2o_w,  const float* __restrict__ h2o_b,
    const float* __restrict__ tau_adp_h1, const float* __restrict__ tau_adp_h2,
    const float* __restrict__ tau_adp_h3,
    const float* __restrict__ tau_m_h1,   const float* __restrict__ tau_m_h2,
    const float* __restrict__ tau_m_h3,
    float* __restrict__ out)
{
    const int j    = threadIdx.x;
    const int warp = j >> 5, lane = j & 31;
    const unsigned lanemask_lt = (1u << lane) - 1u;
    const int smp0 = blockIdx.x * SPB;

    // smem carve-up
    float*    spk   = smem;                                  // 6*H*SPB floats
    float*    zpad  = spk + 6 * H * SPB;                     // 16 floats (zero)
    unsigned* lists = (unsigned*)(zpad + 16);                // 6*H uint32
    int*      cnts  = (int*)(lists + 6 * H);                 // 6
    int*      wcnt  = cnts + 6;                              // NWARP

    int cur = 0;

    {
        float4 z = make_float4(0.f, 0.f, 0.f, 0.f);
#pragma unroll
        for (int b = 0; b < 6; ++b)
            *(float4*)(spk + b * H * SPB + j * SPB) = z;
        if (j < 16) zpad[j] = 0.0f;
        if (j < 6) cnts[j] = 0;
    }

    const float a1 = xla_cephes_expf(__fdiv_rn(-1.0f, tau_m_h1[j]));
    const float a2 = xla_cephes_expf(__fdiv_rn(-1.0f, tau_m_h2[j]));
    const float a3 = xla_cephes_expf(__fdiv_rn(-1.0f, tau_m_h3[j]));
    const float r1 = xla_cephes_expf(__fdiv_rn(-1.0f, tau_adp_h1[j]));
    const float r2 = xla_cephes_expf(__fdiv_rn(-1.0f, tau_adp_h2[j]));
    const float r3 = xla_cephes_expf(__fdiv_rn(-1.0f, tau_adp_h3[j]));
    const float oma1 = __fsub_rn(1.0f, a1), oma2 = __fsub_rn(1.0f, a2),
                oma3 = __fsub_rn(1.0f, a3);
    const float omr1 = __fsub_rn(1.0f, r1), omr2 = __fsub_rn(1.0f, r2),
                omr3 = __fsub_rn(1.0f, r3);

    const float bi1 = i2h1_b[j], bh1 = h2h1_b[j];
    const ull bi2d = dup2(i2h2_b[j]), bh2d = dup2(h2h2_b[j]);
    const ull bi3d = dup2(i2h3_b[j]), bh3d = dup2(h2h3_b[j]);

    float wi1[INW];
    {
        float4 wa = *(const float4*)(i2h1_w + j * INW);
        float4 wb = *(const float4*)(i2h1_w + j * INW + 4);
        wi1[0] = wa.x; wi1[1] = wa.y; wi1[2] = wa.z; wi1[3] = wa.w;
        wi1[4] = wb.x; wi1[5] = wb.y; wi1[6] = wb.z; wi1[7] = wb.w;
    }

    float m1[SPB], m2[SPB], m3[SPB], b1[SPB], b2[SPB], b3[SPB], c3[SPB];
#pragma unroll
    for (int s = 0; s < SPB; ++s) {
        m1[s] = m2[s] = m3[s] = 0.0f;
        b1[s] = b2[s] = b3[s] = 0.01f;
        c3[s] = 0.0f;
    }

    const char* wt_h2h1 = (const char*)(g_wt + 0 * (size_t)MATF + j);
    const char* wt_i2h2 = (const char*)(g_wt + 1 * (size_t)MATF + j);
    const char* wt_h2h2 = (const char*)(g_wt + 2 * (size_t)MATF + j);
    const char* wt_i2h3 = (const char*)(g_wt + 3 * (size_t)MATF + j);
    const char* wt_h2h3 = (const char*)(g_wt + 4 * (size_t)MATF + j);

    __syncthreads();

    for (int t = 0; t < TSTEPS; ++t) {
        const int st = (t * INW < TSTEPS - INW) ? t * INW : (NPIX - INW);

        const int b1c = 0 + cur, b1n = 0 + (cur ^ 1);
        const int b2c = 2 + cur, b2n = 2 + (cur ^ 1);
        const int b3c = 4 + cur, b3n = 4 + (cur ^ 1);
        float* spk1c = spk + b1c * H * SPB;  float* spk1n = spk + b1n * H * SPB;
        float* spk2c = spk + b2c * H * SPB;  float* spk2n = spk + b2n * H * SPB;
        float* spk3c = spk + b3c * H * SPB;  float* spk3n = spk + b3n * H * SPB;

        // ================= layer 1 =================
        ull accH0 = 0ull, accH1 = 0ull;
        event_matvec(lists + b1c * H, cnts[b1c], wt_h2h1, (const char*)spk1c,
                     accH0, accH1);

        float snew[SPB];
        {
            const float* xb = x + (size_t)smp0 * NPIX + st;
            float4 so = *(float4*)(spk1c + j * SPB);
            float sold[SPB] = {so.x, so.y, so.z, so.w};
            ull accp[2] = {accH0, accH1};
#pragma unroll
            for (int s = 0; s < SPB; ++s) {
                float4 xa = *(const float4*)(xb + (size_t)s * NPIX);
                float4 xc = *(const float4*)(xb + (size_t)s * NPIX + 4);
                float dx = __fmaf_rn(xa.x, wi1[0], 0.0f);
                dx = __fmaf_rn(xa.y, wi1[1], dx);
                dx = __fmaf_rn(xa.z, wi1[2], dx);
                dx = __fmaf_rn(xa.w, wi1[3], dx);
                dx = __fmaf_rn(xc.x, wi1[4], dx);
                dx = __fmaf_rn(xc.y, wi1[5], dx);
                dx = __fmaf_rn(xc.z, wi1[6], dx);
                dx = __fmaf_rn(xc.w, wi1[7], dx);
                float2 dh2 = unpack2(accp[s >> 1]);
                float dh = (s & 1) ? dh2.y : dh2.x;
                float h = __fadd_rn(__fadd_rn(__fadd_rn(dx, bi1), dh), bh1);
                alif_step(h, m1[s], b1[s], sold[s], a1, oma1, r1, omr1, snew[s]);
            }
        }
        {
            *(float4*)(spk1n + j * SPB) = make_float4(snew[0], snew[1], snew[2], snew[3]);
            bool any = (snew[0] + snew[1] + snew[2] + snew[3]) > 0.0f;
            unsigned mask = __ballot_sync(0xffffffffu, any);
            if (lane == 0) wcnt[warp] = __popc(mask);
            __syncthreads();
            int base = 0, total = 0;
#pragma unroll
            for (int w = 0; w < NWARP; ++w) {
                int c = wcnt[w];
                if (w < warp) base += c;
                total += c;
            }
            if (any) lists[b1n * H + base + __popc(mask & lanemask_lt)] = (unsigned)(j * 16);
            if (j == 0) {
                int padded = (total + 7) & ~7;
                for (int k = total; k < padded; ++k)
                    lists[b1n * H + k] = (unsigned)(H * 16);
                cnts[b1n] = padded;
            }
            __syncthreads();
        }

        // ================= layer 2 =================
        ull accI0 = 0ull, accI1 = 0ull;
        accH0 = 0ull; accH1 = 0ull;
        event_matvec(lists + b1n * H, cnts[b1n], wt_i2h2, (const char*)spk1n,
                     accI0, accI1);
        event_matvec(lists + b2c * H, cnts[b2c], wt_h2h2, (const char*)spk2c,
                     accH0, accH1);
        {
            float4 so = *(float4*)(spk2c + j * SPB);
            float sold[SPB] = {so.x, so.y, so.z, so.w};
            ull accIp[2] = {accI0, accI1};
            ull accHp[2] = {accH0, accH1};
#pragma unroll
            for (int q = 0; q < 2; ++q) {
                ull h2v = add2(add2(add2(accIp[q], bi2d), accHp[q]), bh2d);
                float2 hv = unpack2(h2v);
                alif_step(hv.x, m2[2*q],   b2[2*q],   sold[2*q],   a2, oma2, r2, omr2, snew[2*q]);
                alif_step(hv.y, m2[2*q+1], b2[2*q+1], sold[2*q+1], a2, oma2, r2, omr2, snew[2*q+1]);
            }
        }
        {
            *(float4*)(spk2n + j * SPB) = make_float4(snew[0], snew[1], snew[2], snew[3]);
            bool any = (snew[0] + snew[1] + snew[2] + snew[3]) > 0.0f;
            unsigned mask = __ballot_sync(0xffffffffu, any);
            if (lane == 0) wcnt[warp] = __popc(mask);
            __syncthreads();
            int base = 0, total = 0;
#pragma unroll
            for (int w = 0; w < NWARP; ++w) {
                int c = wcnt[w];
                if (w < warp) base += c;
                total += c;
            }
            if (any) lists[b2n * H + base + __popc(mask & lanemask_lt)] = (unsigned)(j * 16);
            if (j == 0) {
                int padded = (total + 7) & ~7;
                for (int k = total; k < padded; ++k)
                    lists[b2n * H + k] = (unsigned)(H * 16);
                cnts[b2n] = padded;
            }
            __syncthreads();
        }

        // ================= layer 3 =================
        accI0 = 0ull; accI1 = 0ull;
        accH0 = 0ull; accH1 = 0ull;
        event_matvec(lists + b2n * H, cnts[b2n], wt_i2h3, (const char*)spk2n,
                     accI0, accI1);
        event_matvec(lists + b3c * H, cnts[b3c], wt_h2h3, (const char*)spk3c,
                     accH0, accH1);
        {
            float4 so = *(float4*)(spk3c + j * SPB);
            float sold[SPB] = {so.x, so.y, so.z, so.w};
            ull accIp[2] = {accI0, accI1};
            ull accHp[2] = {accH0, accH1};
#pragma unroll
            for (int q = 0; q < 2; ++q) {
                ull h2v = add2(add2(add2(accIp[q], bi3d), accHp[q]), bh3d);
                float2 hv = unpack2(h2v);
                alif_step(hv.x, m3[2*q],   b3[2*q],   sold[2*q],   a3, oma3, r3, omr3, snew[2*q]);
                alif_step(hv.y, m3[2*q+1], b3[2*q+1], sold[2*q+1], a3, oma3, r3, omr3, snew[2*q+1]);
            }
        }
        {
            *(float4*)(spk3n + j * SPB) = make_float4(snew[0], snew[1], snew[2], snew[3]);
            bool any = (snew[0] + snew[1] + snew[2] + snew[3]) > 0.0f;
            unsigned mask = __ballot_sync(0xffffffffu, any);
            if (lane == 0) wcnt[warp] = __popc(mask);
            __syncthreads();
            int base = 0, total = 0;
#pragma unroll
            for (int w = 0; w < NWARP; ++w) {
                int c = wcnt[w];
                if (w < warp) base += c;
                total += c;
            }
            if (any) lists[b3n * H + base + __popc(mask & lanemask_lt)] = (unsigned)(j * 16);
            if (j == 0) {
                int padded = (total + 7) & ~7;
                for (int k = total; k < padded; ++k)
                    lists[b3n * H + k] = (unsigned)(H * 16);
                cnts[b3n] = padded;
            }
#pragma unroll
            for (int s = 0; s < SPB; ++s) c3[s] += snew[s];
            __syncthreads();
        }

        cur ^= 1;
    }

    // ======== output: out[smp][o] = (sum_j c3[smp][j]*W[o][j]) / T + b[o] ========
    __syncthreads();
#pragma unroll
    for (int s = 0; s < SPB; ++s) spk[s * H + j] = c3[s];
    __syncthreads();

    for (int pair = warp; pair < SPB * OUTN; pair += NWARP) {
        int s = pair / OUTN, o = pair % OUTN;
        float sum = 0.0f;
        for (int jj = lane; jj < H; jj += 32)
            sum += spk[s * H + jj] * __ldg(h2o_w + o * H + jj);
#pragma unroll
        for (int off = 16; off > 0; off >>= 1)
            sum += __shfl_down_sync(0xffffffffu, sum, off);
        if (lane == 0)
            out[(size_t)(smp0 + s) * OUTN + o] = sum / (float)TSTEPS + h2o_b[o];
    }
}

// ---------------------------------------------------------------------------
extern "C" void kernel_launch(void* const* d_in, const int* in_sizes, int n_in,
                              void* d_out, int out_size) {
    (void)in_sizes; (void)n_in; (void)out_size;
    const float* x          = (const float*)d_in[0];
    const float* i2h1_w     = (const float*)d_in[1];
    const float* i2h1_b     = (const float*)d_in[2];
    const float* h2h1_w     = (const float*)d_in[3];
    const float* h2h1_b     = (const float*)d_in[4];
    const float* i2h2_w     = (const float*)d_in[5];
    const float* i2h2_b     = (const float*)d_in[6];
    const float* h2h2_w     = (const float*)d_in[7];
    const float* h2h2_b     = (const float*)d_in[8];
    const float* i2h3_w     = (const float*)d_in[9];
    const float* i2h3_b     = (const float*)d_in[10];
    const float* h2h3_w     = (const float*)d_in[11];
    const float* h2h3_b     = (const float*)d_in[12];
    const float* h2o_w      = (const float*)d_in[13];
    const float* h2o_b      = (const float*)d_in[14];
    const float* tau_adp_h1 = (const float*)d_in[15];
    const float* tau_adp_h2 = (const float*)d_in[16];
    const float* tau_adp_h3 = (const float*)d_in[17];
    const float* tau_m_h1   = (const float*)d_in[18];
    const float* tau_m_h2   = (const float*)d_in[19];
    const float* tau_m_h3   = (const float*)d_in[20];
    float* out = (float*)d_out;

    transpose5_kernel<<<dim3(16, 16, 5), dim3(32, 32)>>>(h2h1_w, i2h2_w, h2h2_w,
                                                         i2h3_w, h2h3_w);

    // smem: 6 spike bufs (48KB) + zero pad (64B) + 6 uint32 lists (12KB) + counts
    const size_t smem_bytes = 6 * H * SPB * sizeof(float) + 16 * sizeof(float)
                            + 6 * H * sizeof(unsigned)
                            + (6 + NWARP) * sizeof(int);
    static int attr_set = 0;
    if (!attr_set) {
        cudaFuncSetAttribute(srnn_kernel,
                             cudaFuncAttributeMaxDynamicSharedMemorySize,
                             (int)smem_bytes);
        attr_set = 1;
    }
    srnn_kernel<<<NBLK, NTHR, smem_bytes>>>(
        x, i2h1_w, i2h1_b, h2h1_b, i2h2_b, h2h2_b, i2h3_b, h2h3_b,
        h2o_w, h2o_b, tau_adp_h1, tau_adp_h2, tau_adp_h3,
        tau_m_h1, tau_m_h2, tau_m_h3, out);
}